// round 1
// baseline (speedup 1.0000x reference)
#include <cuda_runtime.h>
#include <cuda_bf16.h>

#define BN_EPS 1e-3f
#define CIN 16
#define C1  64
#define C2  128
#define MAXS 20000

// ---------------- device scratch (no allocations allowed) ----------------
__device__ float d_W1f[C1 * CIN];    // [c][k]
__device__ float d_b1f[C1];
__device__ float d_W2af[C2 * CIN];   // [c][k]
__device__ float d_b2af[C2];
__device__ float d_W2bf[C2 * C1];    // [k][j]
__device__ float d_b2bf[C1];
__device__ float d_segsum[MAXS * C1];
__device__ int   d_segmax[MAXS * C1];
__device__ int   d_poolmax[C1];

// ---------------- fold BN into linear layers ----------------
__global__ void fold_kernel(
    const float* __restrict__ W1,  const float* __restrict__ g1,  const float* __restrict__ b1,
    const float* __restrict__ m1,  const float* __restrict__ v1,
    const float* __restrict__ W2a, const float* __restrict__ g2a, const float* __restrict__ b2a,
    const float* __restrict__ m2a, const float* __restrict__ v2a,
    const float* __restrict__ W2b, const float* __restrict__ g2b, const float* __restrict__ b2b,
    const float* __restrict__ m2b, const float* __restrict__ v2b)
{
    int t = blockIdx.x * blockDim.x + threadIdx.x;
    int stride = gridDim.x * blockDim.x;

    for (int i = t; i < C1 * CIN; i += stride) {
        int c = i / CIN, k = i % CIN;
        float s = g1[c] / sqrtf(v1[c] + BN_EPS);
        d_W1f[i] = W1[k * C1 + c] * s;             // W1 is [Cin, Cout]
    }
    for (int c = t; c < C1; c += stride) {
        float s1 = g1[c] / sqrtf(v1[c] + BN_EPS);
        d_b1f[c] = b1[c] - m1[c] * s1;
        float sb = g2b[c] / sqrtf(v2b[c] + BN_EPS);
        d_b2bf[c] = b2b[c] - m2b[c] * sb;
        d_poolmax[c] = 0;
    }
    for (int i = t; i < C2 * CIN; i += stride) {
        int c = i / CIN, k = i % CIN;
        float s = g2a[c] / sqrtf(v2a[c] + BN_EPS);
        d_W2af[i] = W2a[k * C2 + c] * s;           // W2a is [Cin, 2C]
    }
    for (int c = t; c < C2; c += stride) {
        float s = g2a[c] / sqrtf(v2a[c] + BN_EPS);
        d_b2af[c] = b2a[c] - m2a[c] * s;
    }
    for (int i = t; i < C2 * C1; i += stride) {
        int j = i % C1;
        float s = g2b[j] / sqrtf(v2b[j] + BN_EPS);
        d_W2bf[i] = W2b[i] * s;                    // W2b is [2C, C], same layout
    }
}

__global__ void init_kernel(int S)
{
    int i = blockIdx.x * blockDim.x + threadIdx.x;
    if (i < S * C1) { d_segsum[i] = 0.0f; d_segmax[i] = 0; }
}

// ---------------- main fused MLP + reductions ----------------
__device__ __forceinline__ float dot16(float4 i0, float4 i1, float4 i2, float4 i3,
                                       const float* __restrict__ w)
{
    const float4* wv = (const float4*)w;
    float4 w0 = wv[0], w1 = wv[1], w2 = wv[2], w3 = wv[3];
    float a = i0.x * w0.x + i0.y * w0.y + i0.z * w0.z + i0.w * w0.w;
    float b = i1.x * w1.x + i1.y * w1.y + i1.z * w1.z + i1.w * w1.w;
    float c = i2.x * w2.x + i2.y * w2.y + i2.z * w2.z + i2.w * w2.w;
    float d = i3.x * w3.x + i3.y * w3.y + i3.z * w3.z + i3.w * w3.w;
    return (a + b) + (c + d);
}

__global__ __launch_bounds__(128, 1)
void main_kernel(const float* __restrict__ inp, const int* __restrict__ seg, int N)
{
    __shared__ float sW1[C1 * CIN];
    __shared__ float sW2a[C2 * CIN];
    __shared__ float sW2b[C2 * C1];
    __shared__ float sb1[C1], sb2a[C2], sb2b[C1];
    __shared__ int   spool[C1];

    const int tx = threadIdx.x;
    for (int i = tx; i < C1 * CIN; i += 128) sW1[i]  = d_W1f[i];
    for (int i = tx; i < C2 * CIN; i += 128) sW2a[i] = d_W2af[i];
    for (int i = tx; i < C2 * C1;  i += 128) sW2b[i] = d_W2bf[i];
    if (tx < C1) { sb1[tx] = d_b1f[tx]; sb2b[tx] = d_b2bf[tx]; spool[tx] = 0; }
    if (tx < C2) { sb2a[tx] = d_b2af[tx]; }
    __syncthreads();

    float pool[C1];
#pragma unroll
    for (int j = 0; j < C1; j++) pool[j] = 0.0f;

    const int stride = gridDim.x * 128;
    for (int r = blockIdx.x * 128 + tx; r < N; r += stride) {
        const float4* ip = (const float4*)(inp + (size_t)r * CIN);
        float4 i0 = ip[0], i1 = ip[1], i2 = ip[2], i3 = ip[3];
        int sg = seg[r];
        float* sumb = d_segsum + (size_t)sg * C1;
        int*   maxb = d_segmax + (size_t)sg * C1;

        // branch 1: 16 -> 64, ReLU, segment sum + segment max via atomics
#pragma unroll 4
        for (int c = 0; c < C1; c++) {
            float x = fmaxf(sb1[c] + dot16(i0, i1, i2, i3, sW1 + c * CIN), 0.0f);
            atomicAdd(sumb + c, x);
            atomicMax(maxb + c, __float_as_int(x));   // x >= 0: float bits monotonic
        }

        // branch 2: 16 -> 128 (ReLU) -> 64, fold into global channel max
        float acc[C1];
#pragma unroll
        for (int j = 0; j < C1; j++) acc[j] = sb2b[j];

#pragma unroll 1
        for (int k = 0; k < C2; k++) {
            float h = fmaxf(sb2a[k] + dot16(i0, i1, i2, i3, sW2a + k * CIN), 0.0f);
            const float4* wb = (const float4*)(sW2b + k * C1);
#pragma unroll
            for (int j4 = 0; j4 < 16; j4++) {
                float4 w = wb[j4];
                acc[4 * j4 + 0] += h * w.x;
                acc[4 * j4 + 1] += h * w.y;
                acc[4 * j4 + 2] += h * w.z;
                acc[4 * j4 + 3] += h * w.w;
            }
        }
#pragma unroll
        for (int j = 0; j < C1; j++) pool[j] = fmaxf(pool[j], acc[j]);
    }

    // global channel max: warp reduce -> smem -> one block-level global atomic
#pragma unroll
    for (int j = 0; j < C1; j++) {
        int v = __float_as_int(fmaxf(pool[j], 0.0f));
        v = __reduce_max_sync(0xffffffffu, v);
        if ((tx & 31) == 0) atomicMax(&spool[j], v);
    }
    __syncthreads();
    if (tx < C1) atomicMax(&d_poolmax[tx], spool[tx]);
}

// ---------------- finalize: channel shuffle into output ----------------
__global__ void finalize_kernel(float* __restrict__ out, int S)
{
    int i = blockIdx.x * blockDim.x + threadIdx.x;
    if (i >= S * C1) return;
    int s = i / C1, c = i % C1;
    float sum = d_segsum[i];
    float mx  = __int_as_float(d_segmax[i]);    // init 0 == clamp for empty segments
    float pl  = __int_as_float(d_poolmax[c]);
    float* o = out + (size_t)s * (3 * C1) + 3 * c;
    o[0] = sum;   // group_sum
    o[1] = mx;    // x_max
    o[2] = pl;    // max_pool broadcast
}

// ---------------- launch ----------------
extern "C" void kernel_launch(void* const* d_in, const int* in_sizes, int n_in,
                              void* d_out, int out_size)
{
    const float* inp = (const float*)d_in[0];
    const int*   seg = (const int*)d_in[1];
    // d_in[2] = num_segments (scalar); S derived from out_size instead
    const float* W1  = (const float*)d_in[3];
    const float* g1  = (const float*)d_in[4];
    const float* b1  = (const float*)d_in[5];
    const float* m1  = (const float*)d_in[6];
    const float* v1  = (const float*)d_in[7];
    const float* W2a = (const float*)d_in[8];
    const float* g2a = (const float*)d_in[9];
    const float* b2a = (const float*)d_in[10];
    const float* m2a = (const float*)d_in[11];
    const float* v2a = (const float*)d_in[12];
    const float* W2b = (const float*)d_in[13];
    const float* g2b = (const float*)d_in[14];
    const float* b2b = (const float*)d_in[15];
    const float* m2b = (const float*)d_in[16];
    const float* v2b = (const float*)d_in[17];

    int N = in_sizes[0] / CIN;
    int S = out_size / (3 * C1);
    if (S > MAXS) S = MAXS;

    fold_kernel<<<16, 256>>>(W1, g1, b1, m1, v1,
                             W2a, g2a, b2a, m2a, v2a,
                             W2b, g2b, b2b, m2b, v2b);

    int ne = S * C1;
    init_kernel<<<(ne + 255) / 256, 256>>>(S);

    main_kernel<<<1776, 128>>>(inp, seg, N);

    finalize_kernel<<<(ne + 255) / 256, 256>>>((float*)d_out, S);
}

// round 3
// speedup vs baseline: 1.0790x; 1.0790x over previous
#include <cuda_runtime.h>
#include <cuda_bf16.h>

#define BN_EPS 1e-3f
#define CIN 16
#define C1  64
#define C2  128
#define MAXS 20000

typedef unsigned long long ull;

// ---------------- device scratch (no allocations allowed) ----------------
__device__ float2 d_W1p[(C1 / 2) * CIN];   // channel-pair p, input i: (w[2p][i], w[2p+1][i])
__device__ float2 d_b1p[C1 / 2];
__device__ float2 d_W2ap[(C2 / 2) * CIN];
__device__ float2 d_b2ap[C2 / 2];
__device__ float  d_W2bf[C2 * C1];         // [k][j], BN-scaled
__device__ float  d_b2bf[C1];
__device__ float  d_segsum[MAXS * C1];
__device__ int    d_segmax[MAXS * C1];
__device__ int    d_poolmax[C1];

// ---------------- f32x2 helpers (sm_100a packed fp32 SIMD) ----------------
__device__ __forceinline__ ull ffma2(ull a, ull b, ull c) {
    ull d;
    asm("fma.rn.f32x2 %0, %1, %2, %3;" : "=l"(d) : "l"(a), "l"(b), "l"(c));
    return d;
}
__device__ __forceinline__ ull fadd2(ull a, ull b) {
    ull d;
    asm("add.rn.f32x2 %0, %1, %2;" : "=l"(d) : "l"(a), "l"(b));
    return d;
}
__device__ __forceinline__ ull pack2(float lo, float hi) {
    ull d;
    asm("mov.b64 %0, {%1, %2};" : "=l"(d) : "f"(lo), "f"(hi));
    return d;
}
__device__ __forceinline__ void unpack2(ull v, float& lo, float& hi) {
    asm("mov.b64 {%0, %1}, %2;" : "=f"(lo), "=f"(hi) : "l"(v));
}

// ---------------- fold BN into linear layers, pre-interleave pairs ----------------
__global__ void fold_kernel(
    const float* __restrict__ W1,  const float* __restrict__ g1,  const float* __restrict__ b1,
    const float* __restrict__ m1,  const float* __restrict__ v1,
    const float* __restrict__ W2a, const float* __restrict__ g2a, const float* __restrict__ b2a,
    const float* __restrict__ m2a, const float* __restrict__ v2a,
    const float* __restrict__ W2b, const float* __restrict__ g2b, const float* __restrict__ b2b,
    const float* __restrict__ m2b, const float* __restrict__ v2b)
{
    int t = blockIdx.x * blockDim.x + threadIdx.x;
    int stride = gridDim.x * blockDim.x;

    // W1: [Cin, C1] -> pair-interleaved [C1/2][CIN] of float2
    for (int i = t; i < (C1 / 2) * CIN; i += stride) {
        int p = i / CIN, k = i % CIN;
        int c0 = 2 * p, c1 = 2 * p + 1;
        float s0 = g1[c0] * rsqrtf(v1[c0] + BN_EPS);
        float s1 = g1[c1] * rsqrtf(v1[c1] + BN_EPS);
        d_W1p[i] = make_float2(W1[k * C1 + c0] * s0, W1[k * C1 + c1] * s1);
    }
    for (int p = t; p < C1 / 2; p += stride) {
        int c0 = 2 * p, c1 = 2 * p + 1;
        float s0 = g1[c0] * rsqrtf(v1[c0] + BN_EPS);
        float s1 = g1[c1] * rsqrtf(v1[c1] + BN_EPS);
        d_b1p[p] = make_float2(b1[c0] - m1[c0] * s0, b1[c1] - m1[c1] * s1);
    }
    // W2a: [Cin, C2] -> pair-interleaved [C2/2][CIN] of float2
    for (int i = t; i < (C2 / 2) * CIN; i += stride) {
        int p = i / CIN, k = i % CIN;
        int c0 = 2 * p, c1 = 2 * p + 1;
        float s0 = g2a[c0] * rsqrtf(v2a[c0] + BN_EPS);
        float s1 = g2a[c1] * rsqrtf(v2a[c1] + BN_EPS);
        d_W2ap[i] = make_float2(W2a[k * C2 + c0] * s0, W2a[k * C2 + c1] * s1);
    }
    for (int p = t; p < C2 / 2; p += stride) {
        int c0 = 2 * p, c1 = 2 * p + 1;
        float s0 = g2a[c0] * rsqrtf(v2a[c0] + BN_EPS);
        float s1 = g2a[c1] * rsqrtf(v2a[c1] + BN_EPS);
        d_b2ap[p] = make_float2(b2a[c0] - m2a[c0] * s0, b2a[c1] - m2a[c1] * s1);
    }
    // W2b: [2C, C] scaled per output channel j (natural layout pairs along j)
    for (int i = t; i < C2 * C1; i += stride) {
        int j = i % C1;
        float s = g2b[j] * rsqrtf(v2b[j] + BN_EPS);
        d_W2bf[i] = W2b[i] * s;
    }
    for (int c = t; c < C1; c += stride) {
        float s = g2b[c] * rsqrtf(v2b[c] + BN_EPS);
        d_b2bf[c] = b2b[c] - m2b[c] * s;
        d_poolmax[c] = 0;
    }
}

__global__ void init_kernel(int S)
{
    int i = blockIdx.x * blockDim.x + threadIdx.x;
    if (i < S * C1) { d_segsum[i] = 0.0f; d_segmax[i] = 0; }
}

// ---------------- main fused MLP + reductions ----------------
__global__ __launch_bounds__(256, 1)
void main_kernel(const float* __restrict__ inp, const int* __restrict__ seg, int N)
{
    __shared__ ull  sW1p[(C1 / 2) * CIN];     // 4 KB
    __shared__ ull  sW2ap[(C2 / 2) * CIN];    // 8 KB
    __shared__ float sW2b[C2 * C1];           // 32 KB
    __shared__ ull  sb1p[C1 / 2];
    __shared__ ull  sb2ap[C2 / 2];
    __shared__ ull  sb2b2[C1 / 2];
    __shared__ int  spool[C1];

    const int tx = threadIdx.x;
    for (int i = tx; i < (C1 / 2) * CIN; i += 256) sW1p[i]  = ((const ull*)d_W1p)[i];
    for (int i = tx; i < (C2 / 2) * CIN; i += 256) sW2ap[i] = ((const ull*)d_W2ap)[i];
    for (int i = tx; i < C2 * C1; i += 256)        sW2b[i]  = d_W2bf[i];
    if (tx < C1 / 2) {
        sb1p[tx]  = ((const ull*)d_b1p)[tx];
        sb2b2[tx] = ((const ull*)d_b2bf)[tx];
    }
    if (tx < C2 / 2)   sb2ap[tx] = ((const ull*)d_b2ap)[tx];
    if (tx < C1)       spool[tx] = 0;
    __syncthreads();

    float pool[C1];
#pragma unroll
    for (int j = 0; j < C1; j++) pool[j] = 0.0f;

    const int stride = gridDim.x * 256;
    for (int r = blockIdx.x * 256 + tx; r < N; r += stride) {
        // load 16 inputs, build duplicated packs (x_i, x_i)
        const float4* ip = (const float4*)(inp + (size_t)r * CIN);
        ull xp[CIN];
#pragma unroll
        for (int q = 0; q < 4; q++) {
            float4 v = ip[q];
            xp[4 * q + 0] = pack2(v.x, v.x);
            xp[4 * q + 1] = pack2(v.y, v.y);
            xp[4 * q + 2] = pack2(v.z, v.z);
            xp[4 * q + 3] = pack2(v.w, v.w);
        }
        int sg = seg[r];
        float* sumb = d_segsum + (size_t)sg * C1;
        int*   maxb = d_segmax + (size_t)sg * C1;

        // ---- branch 1: 16 -> 64 (channel pairs), ReLU, seg sum/max atomics ----
#pragma unroll 1
        for (int p = 0; p < C1 / 2; p++) {
            const ull* w = sW1p + p * CIN;
            ull a0 = sb1p[p], a1 = 0ull;   // 0ull == (0.f, 0.f)
#pragma unroll
            for (int i = 0; i < CIN / 2; i++) {
                a0 = ffma2(xp[2 * i],     w[2 * i],     a0);
                a1 = ffma2(xp[2 * i + 1], w[2 * i + 1], a1);
            }
            a0 = fadd2(a0, a1);
            float x0, x1;
            unpack2(a0, x0, x1);
            x0 = fmaxf(x0, 0.0f);
            x1 = fmaxf(x1, 0.0f);
            atomicAdd(sumb + 2 * p,     x0);
            atomicAdd(sumb + 2 * p + 1, x1);
            atomicMax(maxb + 2 * p,     __float_as_int(x0));
            atomicMax(maxb + 2 * p + 1, __float_as_int(x1));
        }

        // ---- branch 2: 16 -> 128 (ReLU) -> 64, feeds global channel max ----
        ull acc2[C1 / 2];
#pragma unroll
        for (int jp = 0; jp < C1 / 2; jp++) acc2[jp] = sb2b2[jp];

#pragma unroll 1
        for (int p = 0; p < C2 / 2; p++) {
            const ull* w = sW2ap + p * CIN;
            ull a0 = sb2ap[p], a1 = 0ull;
#pragma unroll
            for (int i = 0; i < CIN / 2; i++) {
                a0 = ffma2(xp[2 * i],     w[2 * i],     a0);
                a1 = ffma2(xp[2 * i + 1], w[2 * i + 1], a1);
            }
            a0 = fadd2(a0, a1);
            float h0, h1;
            unpack2(a0, h0, h1);
            h0 = fmaxf(h0, 0.0f);
            h1 = fmaxf(h1, 0.0f);
            ull hh0 = pack2(h0, h0);
            ull hh1 = pack2(h1, h1);
            const ull* r0 = (const ull*)(sW2b + (2 * p) * C1);
            const ull* r1 = r0 + C1 / 2;
#pragma unroll
            for (int jp = 0; jp < C1 / 2; jp++) {
                ull t = ffma2(hh0, r0[jp], acc2[jp]);
                acc2[jp] = ffma2(hh1, r1[jp], t);
            }
        }
        // fold row into running channel max (pool init 0 => implicit final ReLU)
#pragma unroll
        for (int jp = 0; jp < C1 / 2; jp++) {
            float a, b;
            unpack2(acc2[jp], a, b);
            pool[2 * jp]     = fmaxf(pool[2 * jp],     a);
            pool[2 * jp + 1] = fmaxf(pool[2 * jp + 1], b);
        }
    }

    // global channel max: warp reduce -> smem -> one block-level global atomic
#pragma unroll
    for (int j = 0; j < C1; j++) {
        int v = __float_as_int(pool[j]);           // pool >= 0 by construction
        v = __reduce_max_sync(0xffffffffu, v);
        if ((tx & 31) == 0) atomicMax(&spool[j], v);
    }
    __syncthreads();
    if (tx < C1) atomicMax(&d_poolmax[tx], spool[tx]);
}

// ---------------- finalize: channel shuffle into output ----------------
__global__ void finalize_kernel(float* __restrict__ out, int S)
{
    int i = blockIdx.x * blockDim.x + threadIdx.x;
    if (i >= S * C1) return;
    int s = i / C1, c = i % C1;
    float sum = d_segsum[i];
    float mx  = __int_as_float(d_segmax[i]);    // init 0 == clamp for empty segments
    float pl  = __int_as_float(d_poolmax[c]);
    float* o = out + (size_t)s * (3 * C1) + 3 * c;
    o[0] = sum;   // group_sum
    o[1] = mx;    // x_max
    o[2] = pl;    // max_pool broadcast
}

// ---------------- launch ----------------
extern "C" void kernel_launch(void* const* d_in, const int* in_sizes, int n_in,
                              void* d_out, int out_size)
{
    const float* inp = (const float*)d_in[0];
    const int*   seg = (const int*)d_in[1];
    const float* W1  = (const float*)d_in[3];
    const float* g1  = (const float*)d_in[4];
    const float* b1  = (const float*)d_in[5];
    const float* m1  = (const float*)d_in[6];
    const float* v1  = (const float*)d_in[7];
    const float* W2a = (const float*)d_in[8];
    const float* g2a = (const float*)d_in[9];
    const float* b2a = (const float*)d_in[10];
    const float* m2a = (const float*)d_in[11];
    const float* v2a = (const float*)d_in[12];
    const float* W2b = (const float*)d_in[13];
    const float* g2b = (const float*)d_in[14];
    const float* b2b = (const float*)d_in[15];
    const float* m2b = (const float*)d_in[16];
    const float* v2b = (const float*)d_in[17];

    int N = in_sizes[0] / CIN;
    int S = out_size / (3 * C1);
    if (S > MAXS) S = MAXS;

    fold_kernel<<<16, 256>>>(W1, g1, b1, m1, v1,
                             W2a, g2a, b2a, m2a, v2a,
                             W2b, g2b, b2b, m2b, v2b);

    int ne = S * C1;
    init_kernel<<<(ne + 255) / 256, 256>>>(S);

    main_kernel<<<592, 256>>>(inp, seg, N);

    finalize_kernel<<<(ne + 255) / 256, 256>>>((float*)d_out, S);
}

// round 5
// speedup vs baseline: 1.4930x; 1.3837x over previous
#include <cuda_runtime.h>
#include <cuda_bf16.h>

#define BN_EPS 1e-3f
#define CIN 16
#define C1  64
#define C2  128
#define MAXS 20000
#define MAXN 1048576

typedef unsigned long long ull;

// ---------------- device scratch (no allocations allowed) ----------------
__device__ float2 d_W1p[(C1 / 2) * CIN];   // channel-pair p, input i: (w[2p][i], w[2p+1][i])
__device__ float2 d_b1p[C1 / 2];
__device__ float2 d_W2ap[(C2 / 2) * CIN];
__device__ float2 d_b2ap[C2 / 2];
__device__ float  d_W2bf[C2 * C1];         // [k][j], BN-scaled
__device__ float  d_b2bf[C1];
__device__ float  d_segsum[MAXS * C1];
__device__ float  d_segmaxf[MAXS * C1];
__device__ int    d_poolmax[C1];
// sort machinery
__device__ int    d_hist[MAXS];
__device__ int    d_start[MAXS + 1];
__device__ int    d_offs[MAXS];
__device__ int    d_order[MAXN];

// ---------------- f32x2 helpers (sm_100a packed fp32 SIMD) ----------------
__device__ __forceinline__ ull ffma2(ull a, ull b, ull c) {
    ull d;
    asm("fma.rn.f32x2 %0, %1, %2, %3;" : "=l"(d) : "l"(a), "l"(b), "l"(c));
    return d;
}
__device__ __forceinline__ ull fadd2(ull a, ull b) {
    ull d;
    asm("add.rn.f32x2 %0, %1, %2;" : "=l"(d) : "l"(a), "l"(b));
    return d;
}
__device__ __forceinline__ ull pack2(float lo, float hi) {
    ull d;
    asm("mov.b64 %0, {%1, %2};" : "=l"(d) : "f"(lo), "f"(hi));
    return d;
}
__device__ __forceinline__ void unpack2(ull v, float& lo, float& hi) {
    asm("mov.b64 {%0, %1}, %2;" : "=f"(lo), "=f"(hi) : "l"(v));
}

// ---------------- fold BN into linear layers, pre-interleave pairs ----------------
__global__ void fold_kernel(
    const float* __restrict__ W1,  const float* __restrict__ g1,  const float* __restrict__ b1,
    const float* __restrict__ m1,  const float* __restrict__ v1,
    const float* __restrict__ W2a, const float* __restrict__ g2a, const float* __restrict__ b2a,
    const float* __restrict__ m2a, const float* __restrict__ v2a,
    const float* __restrict__ W2b, const float* __restrict__ g2b, const float* __restrict__ b2b,
    const float* __restrict__ m2b, const float* __restrict__ v2b)
{
    int t = blockIdx.x * blockDim.x + threadIdx.x;
    int stride = gridDim.x * blockDim.x;

    for (int i = t; i < (C1 / 2) * CIN; i += stride) {
        int p = i / CIN, k = i % CIN;
        int c0 = 2 * p, c1 = 2 * p + 1;
        float s0 = g1[c0] * rsqrtf(v1[c0] + BN_EPS);
        float s1 = g1[c1] * rsqrtf(v1[c1] + BN_EPS);
        d_W1p[i] = make_float2(W1[k * C1 + c0] * s0, W1[k * C1 + c1] * s1);
    }
    for (int p = t; p < C1 / 2; p += stride) {
        int c0 = 2 * p, c1 = 2 * p + 1;
        float s0 = g1[c0] * rsqrtf(v1[c0] + BN_EPS);
        float s1 = g1[c1] * rsqrtf(v1[c1] + BN_EPS);
        d_b1p[p] = make_float2(b1[c0] - m1[c0] * s0, b1[c1] - m1[c1] * s1);
    }
    for (int i = t; i < (C2 / 2) * CIN; i += stride) {
        int p = i / CIN, k = i % CIN;
        int c0 = 2 * p, c1 = 2 * p + 1;
        float s0 = g2a[c0] * rsqrtf(v2a[c0] + BN_EPS);
        float s1 = g2a[c1] * rsqrtf(v2a[c1] + BN_EPS);
        d_W2ap[i] = make_float2(W2a[k * C2 + c0] * s0, W2a[k * C2 + c1] * s1);
    }
    for (int p = t; p < C2 / 2; p += stride) {
        int c0 = 2 * p, c1 = 2 * p + 1;
        float s0 = g2a[c0] * rsqrtf(v2a[c0] + BN_EPS);
        float s1 = g2a[c1] * rsqrtf(v2a[c1] + BN_EPS);
        d_b2ap[p] = make_float2(b2a[c0] - m2a[c0] * s0, b2a[c1] - m2a[c1] * s1);
    }
    for (int i = t; i < C2 * C1; i += stride) {
        int j = i % C1;
        float s = g2b[j] * rsqrtf(v2b[j] + BN_EPS);
        d_W2bf[i] = W2b[i] * s;
    }
    for (int c = t; c < C1; c += stride) {
        float s = g2b[c] * rsqrtf(v2b[c] + BN_EPS);
        d_b2bf[c] = b2b[c] - m2b[c] * s;
        d_poolmax[c] = 0;
    }
    for (int i = t; i < MAXS; i += stride) d_hist[i] = 0;
}

// ---------------- counting sort: histogram -> scan -> scatter ----------------
__global__ void hist_kernel(const int* __restrict__ seg, int N)
{
    int i = blockIdx.x * blockDim.x + threadIdx.x;
    if (i < N) atomicAdd(&d_hist[seg[i]], 1);
}

__global__ void scan_kernel(int S, int N)   // single block, 1024 threads
{
    int tid = threadIdx.x;
    int per = (S + 1023) / 1024;
    int lo = tid * per;
    int hi = lo + per; if (hi > S) hi = S; if (lo > S) lo = S;

    int local = 0;
    for (int i = lo; i < hi; i++) local += d_hist[i];

    int lane = tid & 31, wid = tid >> 5;
    int v = local;
#pragma unroll
    for (int d = 1; d < 32; d <<= 1) {
        int t2 = __shfl_up_sync(0xffffffffu, v, d);
        if (lane >= d) v += t2;
    }
    __shared__ int wsum[32];
    if (lane == 31) wsum[wid] = v;
    __syncthreads();
    if (wid == 0) {
        int w = wsum[lane];
#pragma unroll
        for (int d = 1; d < 32; d <<= 1) {
            int t2 = __shfl_up_sync(0xffffffffu, w, d);
            if (lane >= d) w += t2;
        }
        wsum[lane] = w;
    }
    __syncthreads();
    int excl = v - local + (wid > 0 ? wsum[wid - 1] : 0);

    int run = excl;
    for (int i = lo; i < hi; i++) {
        int h = d_hist[i];
        d_start[i] = run;
        d_offs[i]  = run;
        run += h;
    }
    if (tid == 0) d_start[S] = N;
}

__global__ void scatter_kernel(const int* __restrict__ seg, int N)
{
    int i = blockIdx.x * blockDim.x + threadIdx.x;
    if (i < N) {
        int pos = atomicAdd(&d_offs[seg[i]], 1);
        d_order[pos] = i;
    }
}

// ---------------- branch 2 only: 16 -> 128 -> 64, global channel max ----------------
__global__ __launch_bounds__(256, 1)
void branch2_kernel(const float* __restrict__ inp, int N)
{
    __shared__ ull  sW2ap[(C2 / 2) * CIN];    // 8 KB
    __shared__ float sW2b[C2 * C1];           // 32 KB
    __shared__ ull  sb2ap[C2 / 2];
    __shared__ ull  sb2b2[C1 / 2];
    __shared__ int  spool[C1];

    const int tx = threadIdx.x;
    for (int i = tx; i < (C2 / 2) * CIN; i += 256) sW2ap[i] = ((const ull*)d_W2ap)[i];
    for (int i = tx; i < C2 * C1; i += 256)        sW2b[i]  = d_W2bf[i];
    if (tx < C1 / 2)  sb2b2[tx] = ((const ull*)d_b2bf)[tx];
    if (tx < C2 / 2)  sb2ap[tx] = ((const ull*)d_b2ap)[tx];
    if (tx < C1)      spool[tx] = 0;
    __syncthreads();

    float pool[C1];
#pragma unroll
    for (int j = 0; j < C1; j++) pool[j] = 0.0f;

    const int stride = gridDim.x * 256;
    for (int r = blockIdx.x * 256 + tx; r < N; r += stride) {
        const float4* ip = (const float4*)(inp + (size_t)r * CIN);
        ull xp[CIN];
#pragma unroll
        for (int q = 0; q < 4; q++) {
            float4 v = ip[q];
            xp[4 * q + 0] = pack2(v.x, v.x);
            xp[4 * q + 1] = pack2(v.y, v.y);
            xp[4 * q + 2] = pack2(v.z, v.z);
            xp[4 * q + 3] = pack2(v.w, v.w);
        }

        ull acc2[C1 / 2];
#pragma unroll
        for (int jp = 0; jp < C1 / 2; jp++) acc2[jp] = sb2b2[jp];

#pragma unroll 1
        for (int p = 0; p < C2 / 2; p++) {
            const ull* w = sW2ap + p * CIN;
            ull a0 = sb2ap[p], a1 = 0ull;
#pragma unroll
            for (int i = 0; i < CIN / 2; i++) {
                a0 = ffma2(xp[2 * i],     w[2 * i],     a0);
                a1 = ffma2(xp[2 * i + 1], w[2 * i + 1], a1);
            }
            a0 = fadd2(a0, a1);
            float h0, h1;
            unpack2(a0, h0, h1);
            h0 = fmaxf(h0, 0.0f);
            h1 = fmaxf(h1, 0.0f);
            ull hh0 = pack2(h0, h0);
            ull hh1 = pack2(h1, h1);
            const ull* r0 = (const ull*)(sW2b + (2 * p) * C1);
            const ull* r1 = r0 + C1 / 2;
#pragma unroll
            for (int jp = 0; jp < C1 / 2; jp++) {
                ull t = ffma2(hh0, r0[jp], acc2[jp]);
                acc2[jp] = ffma2(hh1, r1[jp], t);
            }
        }
#pragma unroll
        for (int jp = 0; jp < C1 / 2; jp++) {
            float a, b;
            unpack2(acc2[jp], a, b);
            pool[2 * jp]     = fmaxf(pool[2 * jp],     a);
            pool[2 * jp + 1] = fmaxf(pool[2 * jp + 1], b);
        }
    }

#pragma unroll
    for (int j = 0; j < C1; j++) {
        int v = __float_as_int(pool[j]);           // pool >= 0 by construction
        v = __reduce_max_sync(0xffffffffu, v);
        if ((tx & 31) == 0) atomicMax(&spool[j], v);
    }
    __syncthreads();
    if (tx < C1) atomicMax(&d_poolmax[tx], spool[tx]);
}

// ---------------- branch 1 consumer-side: one warp per segment, no atomics ----------------
__global__ __launch_bounds__(256, 2)
void seg_kernel(const float* __restrict__ inp, int S)
{
    __shared__ ull sW1t[CIN * 32];   // transposed: [i][pair]  (conflict-free lane reads)
    __shared__ ull sb1s[32];

    const int tx = threadIdx.x;
    for (int i = tx; i < CIN * 32; i += 256) {
        int row = i >> 5, p = i & 31;
        sW1t[i] = ((const ull*)d_W1p)[p * CIN + row];
    }
    if (tx < 32) sb1s[tx] = ((const ull*)d_b1p)[tx];
    __syncthreads();

    const int gw = (blockIdx.x * 256 + tx) >> 5;   // segment id
    const int lane = tx & 31;                      // channel pair
    if (gw >= S) return;

    ull w[CIN];
#pragma unroll
    for (int i = 0; i < CIN; i++) w[i] = sW1t[(i << 5) | lane];
    const ull bias = sb1s[lane];

    const int s0 = d_start[gw], s1 = d_start[gw + 1];
    ull   sum2 = 0ull;
    float mx0 = 0.0f, mx1 = 0.0f;

    if (s0 < s1) {
        // 2-stage software pipeline: row index two ahead, row data one ahead
        int r  = d_order[s0];
        int rn = (s0 + 1 < s1) ? d_order[s0 + 1] : 0;
        const float4* ip = (const float4*)(inp + (size_t)r * CIN);
        float4 Va = ip[0], Vb = ip[1], Vc = ip[2], Vd = ip[3];

        for (int idx = s0; idx < s1; idx++) {
            int rn2 = (idx + 2 < s1) ? d_order[idx + 2] : 0;
            float4 Pa, Pb, Pc, Pd;
            if (idx + 1 < s1) {
                const float4* ipn = (const float4*)(inp + (size_t)rn * CIN);
                Pa = ipn[0]; Pb = ipn[1]; Pc = ipn[2]; Pd = ipn[3];
            }

            float xs[CIN] = {Va.x, Va.y, Va.z, Va.w, Vb.x, Vb.y, Vb.z, Vb.w,
                             Vc.x, Vc.y, Vc.z, Vc.w, Vd.x, Vd.y, Vd.z, Vd.w};
            ull a0 = bias, a1 = 0ull;
#pragma unroll
            for (int i = 0; i < CIN / 2; i++) {
                a0 = ffma2(pack2(xs[2 * i],     xs[2 * i]),     w[2 * i],     a0);
                a1 = ffma2(pack2(xs[2 * i + 1], xs[2 * i + 1]), w[2 * i + 1], a1);
            }
            a0 = fadd2(a0, a1);
            float x0, x1;
            unpack2(a0, x0, x1);
            x0 = fmaxf(x0, 0.0f);
            x1 = fmaxf(x1, 0.0f);
            sum2 = fadd2(sum2, pack2(x0, x1));
            mx0 = fmaxf(mx0, x0);
            mx1 = fmaxf(mx1, x1);

            r = rn; rn = rn2;
            Va = Pa; Vb = Pb; Vc = Pc; Vd = Pd;
        }
    }

    float sA, sB;
    unpack2(sum2, sA, sB);
    d_segsum[gw * C1 + 2 * lane]      = sA;
    d_segsum[gw * C1 + 2 * lane + 1]  = sB;
    d_segmaxf[gw * C1 + 2 * lane]     = mx0;   // >=0, empty segment -> 0 (matches clamp)
    d_segmaxf[gw * C1 + 2 * lane + 1] = mx1;
}

// ---------------- finalize: channel shuffle into output ----------------
__global__ void finalize_kernel(float* __restrict__ out, int S)
{
    int i = blockIdx.x * blockDim.x + threadIdx.x;
    if (i >= S * C1) return;
    int s = i / C1, c = i % C1;
    float sum = d_segsum[i];
    float mx  = d_segmaxf[i];
    float pl  = __int_as_float(d_poolmax[c]);
    float* o = out + (size_t)s * (3 * C1) + 3 * c;
    o[0] = sum;   // group_sum
    o[1] = mx;    // x_max
    o[2] = pl;    // max_pool broadcast
}

// ---------------- launch ----------------
extern "C" void kernel_launch(void* const* d_in, const int* in_sizes, int n_in,
                              void* d_out, int out_size)
{
    const float* inp = (const float*)d_in[0];
    const int*   seg = (const int*)d_in[1];
    const float* W1  = (const float*)d_in[3];
    const float* g1  = (const float*)d_in[4];
    const float* b1  = (const float*)d_in[5];
    const float* m1  = (const float*)d_in[6];
    const float* v1  = (const float*)d_in[7];
    const float* W2a = (const float*)d_in[8];
    const float* g2a = (const float*)d_in[9];
    const float* b2a = (const float*)d_in[10];
    const float* m2a = (const float*)d_in[11];
    const float* v2a = (const float*)d_in[12];
    const float* W2b = (const float*)d_in[13];
    const float* g2b = (const float*)d_in[14];
    const float* b2b = (const float*)d_in[15];
    const float* m2b = (const float*)d_in[16];
    const float* v2b = (const float*)d_in[17];

    int N = in_sizes[0] / CIN;
    if (N > MAXN) N = MAXN;
    int S = out_size / (3 * C1);
    if (S > MAXS) S = MAXS;

    fold_kernel<<<16, 256>>>(W1, g1, b1, m1, v1,
                             W2a, g2a, b2a, m2a, v2a,
                             W2b, g2b, b2b, m2b, v2b);

    hist_kernel<<<(N + 255) / 256, 256>>>(seg, N);
    scan_kernel<<<1, 1024>>>(S, N);
    scatter_kernel<<<(N + 255) / 256, 256>>>(seg, N);

    branch2_kernel<<<592, 256>>>(inp, N);

    seg_kernel<<<(S * 32 + 255) / 256, 256>>>(inp, S);

    int ne = S * C1;
    finalize_kernel<<<(ne + 255) / 256, 256>>>((float*)d_out, S);
}

// round 6
// speedup vs baseline: 1.5029x; 1.0066x over previous
#include <cuda_runtime.h>
#include <cuda_bf16.h>

#define BN_EPS 1e-3f
#define CIN 16
#define C1  64
#define C2  128
#define MAXS 20000
#define MAXN 1048576

typedef unsigned long long ull;

// ---------------- device scratch (no allocations allowed) ----------------
__device__ float2 d_W1p[(C1 / 2) * CIN];   // channel-pair p, input i: (w[2p][i], w[2p+1][i])
__device__ float2 d_b1p[C1 / 2];
__device__ float2 d_W2ap[(C2 / 2) * CIN];
__device__ float2 d_b2ap[C2 / 2];
__device__ float  d_W2bf[C2 * C1];         // [k][j], BN-scaled
__device__ float  d_b2bf[C1];
__device__ float  d_segsum[MAXS * C1];
__device__ float  d_segmaxf[MAXS * C1];
__device__ int    d_poolmax[C1];
// sort machinery
__device__ int    d_hist[MAXS];
__device__ int    d_start[MAXS + 1];
__device__ int    d_offs[MAXS];
__device__ int    d_order[MAXN];

// ---------------- f32x2 helpers (sm_100a packed fp32 SIMD) ----------------
__device__ __forceinline__ ull ffma2(ull a, ull b, ull c) {
    ull d;
    asm("fma.rn.f32x2 %0, %1, %2, %3;" : "=l"(d) : "l"(a), "l"(b), "l"(c));
    return d;
}
__device__ __forceinline__ ull fadd2(ull a, ull b) {
    ull d;
    asm("add.rn.f32x2 %0, %1, %2;" : "=l"(d) : "l"(a), "l"(b));
    return d;
}
__device__ __forceinline__ ull pack2(float lo, float hi) {
    ull d;
    asm("mov.b64 %0, {%1, %2};" : "=l"(d) : "f"(lo), "f"(hi));
    return d;
}
__device__ __forceinline__ void unpack2(ull v, float& lo, float& hi) {
    asm("mov.b64 {%0, %1}, %2;" : "=f"(lo), "=f"(hi) : "l"(v));
}

// ---------------- fold BN into linear layers, pre-interleave pairs ----------------
__global__ void fold_kernel(
    const float* __restrict__ W1,  const float* __restrict__ g1,  const float* __restrict__ b1,
    const float* __restrict__ m1,  const float* __restrict__ v1,
    const float* __restrict__ W2a, const float* __restrict__ g2a, const float* __restrict__ b2a,
    const float* __restrict__ m2a, const float* __restrict__ v2a,
    const float* __restrict__ W2b, const float* __restrict__ g2b, const float* __restrict__ b2b,
    const float* __restrict__ m2b, const float* __restrict__ v2b)
{
    int t = blockIdx.x * blockDim.x + threadIdx.x;
    int stride = gridDim.x * blockDim.x;

    for (int i = t; i < (C1 / 2) * CIN; i += stride) {
        int p = i / CIN, k = i % CIN;
        int c0 = 2 * p, c1 = 2 * p + 1;
        float s0 = g1[c0] * rsqrtf(v1[c0] + BN_EPS);
        float s1 = g1[c1] * rsqrtf(v1[c1] + BN_EPS);
        d_W1p[i] = make_float2(W1[k * C1 + c0] * s0, W1[k * C1 + c1] * s1);
    }
    for (int p = t; p < C1 / 2; p += stride) {
        int c0 = 2 * p, c1 = 2 * p + 1;
        float s0 = g1[c0] * rsqrtf(v1[c0] + BN_EPS);
        float s1 = g1[c1] * rsqrtf(v1[c1] + BN_EPS);
        d_b1p[p] = make_float2(b1[c0] - m1[c0] * s0, b1[c1] - m1[c1] * s1);
    }
    for (int i = t; i < (C2 / 2) * CIN; i += stride) {
        int p = i / CIN, k = i % CIN;
        int c0 = 2 * p, c1 = 2 * p + 1;
        float s0 = g2a[c0] * rsqrtf(v2a[c0] + BN_EPS);
        float s1 = g2a[c1] * rsqrtf(v2a[c1] + BN_EPS);
        d_W2ap[i] = make_float2(W2a[k * C2 + c0] * s0, W2a[k * C2 + c1] * s1);
    }
    for (int p = t; p < C2 / 2; p += stride) {
        int c0 = 2 * p, c1 = 2 * p + 1;
        float s0 = g2a[c0] * rsqrtf(v2a[c0] + BN_EPS);
        float s1 = g2a[c1] * rsqrtf(v2a[c1] + BN_EPS);
        d_b2ap[p] = make_float2(b2a[c0] - m2a[c0] * s0, b2a[c1] - m2a[c1] * s1);
    }
    for (int i = t; i < C2 * C1; i += stride) {
        int j = i % C1;
        float s = g2b[j] * rsqrtf(v2b[j] + BN_EPS);
        d_W2bf[i] = W2b[i] * s;
    }
    for (int c = t; c < C1; c += stride) {
        float s = g2b[c] * rsqrtf(v2b[c] + BN_EPS);
        d_b2bf[c] = b2b[c] - m2b[c] * s;
        d_poolmax[c] = 0;
    }
    for (int i = t; i < MAXS; i += stride) d_hist[i] = 0;
}

// ---------------- counting sort: histogram -> scan -> scatter ----------------
__global__ void hist_kernel(const int* __restrict__ seg, int N)
{
    int i = blockIdx.x * blockDim.x + threadIdx.x;
    if (i < N) atomicAdd(&d_hist[seg[i]], 1);
}

__global__ void scan_kernel(int S, int N)   // single block, 1024 threads
{
    int tid = threadIdx.x;
    int per = (S + 1023) / 1024;
    int lo = tid * per;
    int hi = lo + per; if (hi > S) hi = S; if (lo > S) lo = S;

    int local = 0;
    for (int i = lo; i < hi; i++) local += d_hist[i];

    int lane = tid & 31, wid = tid >> 5;
    int v = local;
#pragma unroll
    for (int d = 1; d < 32; d <<= 1) {
        int t2 = __shfl_up_sync(0xffffffffu, v, d);
        if (lane >= d) v += t2;
    }
    __shared__ int wsum[32];
    if (lane == 31) wsum[wid] = v;
    __syncthreads();
    if (wid == 0) {
        int w = wsum[lane];
#pragma unroll
        for (int d = 1; d < 32; d <<= 1) {
            int t2 = __shfl_up_sync(0xffffffffu, w, d);
            if (lane >= d) w += t2;
        }
        wsum[lane] = w;
    }
    __syncthreads();
    int excl = v - local + (wid > 0 ? wsum[wid - 1] : 0);

    int run = excl;
    for (int i = lo; i < hi; i++) {
        int h = d_hist[i];
        d_start[i] = run;
        d_offs[i]  = run;
        run += h;
    }
    if (tid == 0) d_start[S] = N;
}

__global__ void scatter_kernel(const int* __restrict__ seg, int N)
{
    int i = blockIdx.x * blockDim.x + threadIdx.x;
    if (i < N) {
        int pos = atomicAdd(&d_offs[seg[i]], 1);
        d_order[pos] = i;
    }
}

// ---------------- branch 2: 16 -> 128 -> 64, global channel max ----------------
// 2 rows per thread: weight LDS (sW2ap + sW2b rows) shared across both rows.
__global__ __launch_bounds__(128, 2)
void branch2_kernel(const float* __restrict__ inp, int N)
{
    __shared__ ull  sW2ap[(C2 / 2) * CIN];    // 8 KB
    __shared__ float sW2b[C2 * C1];           // 32 KB
    __shared__ ull  sb2ap[C2 / 2];
    __shared__ ull  sb2b2[C1 / 2];
    __shared__ int  spool[C1];

    const int tx = threadIdx.x;
    for (int i = tx; i < (C2 / 2) * CIN; i += 128) sW2ap[i] = ((const ull*)d_W2ap)[i];
    for (int i = tx; i < C2 * C1; i += 128)        sW2b[i]  = d_W2bf[i];
    if (tx < C1 / 2)  sb2b2[tx] = ((const ull*)d_b2bf)[tx];
    if (tx < C2 / 2)  sb2ap[tx] = ((const ull*)d_b2ap)[tx];
    if (tx < C1)      spool[tx] = 0;
    __syncthreads();

    float pool[C1];
#pragma unroll
    for (int j = 0; j < C1; j++) pool[j] = 0.0f;

    const int tstride = gridDim.x * 128 * 2;
    for (int base = (blockIdx.x * 128 + tx) * 2; base < N; base += tstride) {
        const int r0 = base;
        const int r1 = base + 1;
        const bool has1 = (r1 < N);

        const float4* ipA = (const float4*)(inp + (size_t)r0 * CIN);
        const float4* ipB = (const float4*)(inp + (size_t)(has1 ? r1 : r0) * CIN);
        ull xpA[CIN], xpB[CIN];
#pragma unroll
        for (int q = 0; q < 4; q++) {
            float4 va = ipA[q];
            xpA[4 * q + 0] = pack2(va.x, va.x);
            xpA[4 * q + 1] = pack2(va.y, va.y);
            xpA[4 * q + 2] = pack2(va.z, va.z);
            xpA[4 * q + 3] = pack2(va.w, va.w);
            float4 vb = ipB[q];
            xpB[4 * q + 0] = pack2(vb.x, vb.x);
            xpB[4 * q + 1] = pack2(vb.y, vb.y);
            xpB[4 * q + 2] = pack2(vb.z, vb.z);
            xpB[4 * q + 3] = pack2(vb.w, vb.w);
        }

        ull accA[C1 / 2], accB[C1 / 2];
#pragma unroll
        for (int jp = 0; jp < C1 / 2; jp++) { accA[jp] = sb2b2[jp]; accB[jp] = sb2b2[jp]; }

#pragma unroll 1
        for (int p = 0; p < C2 / 2; p++) {
            const ull* w = sW2ap + p * CIN;
            ull a0 = sb2ap[p], a1 = 0ull;
            ull c0 = sb2ap[p], c1 = 0ull;
#pragma unroll
            for (int i = 0; i < CIN / 2; i++) {
                ull w0 = w[2 * i], w1 = w[2 * i + 1];
                a0 = ffma2(xpA[2 * i],     w0, a0);
                a1 = ffma2(xpA[2 * i + 1], w1, a1);
                c0 = ffma2(xpB[2 * i],     w0, c0);
                c1 = ffma2(xpB[2 * i + 1], w1, c1);
            }
            a0 = fadd2(a0, a1);
            c0 = fadd2(c0, c1);
            float hA0, hA1, hB0, hB1;
            unpack2(a0, hA0, hA1);
            unpack2(c0, hB0, hB1);
            hA0 = fmaxf(hA0, 0.0f); hA1 = fmaxf(hA1, 0.0f);
            hB0 = fmaxf(hB0, 0.0f); hB1 = fmaxf(hB1, 0.0f);
            ull hhA0 = pack2(hA0, hA0), hhA1 = pack2(hA1, hA1);
            ull hhB0 = pack2(hB0, hB0), hhB1 = pack2(hB1, hB1);
            const ull* w2b0 = (const ull*)(sW2b + (2 * p) * C1);
            const ull* w2b1 = w2b0 + C1 / 2;
#pragma unroll
            for (int jp = 0; jp < C1 / 2; jp++) {
                ull w0 = w2b0[jp];          // shared by both rows
                ull w1 = w2b1[jp];
                ull tA = ffma2(hhA0, w0, accA[jp]);
                accA[jp] = ffma2(hhA1, w1, tA);
                ull tB = ffma2(hhB0, w0, accB[jp]);
                accB[jp] = ffma2(hhB1, w1, tB);
            }
        }
#pragma unroll
        for (int jp = 0; jp < C1 / 2; jp++) {
            float a, b;
            unpack2(accA[jp], a, b);
            pool[2 * jp]     = fmaxf(pool[2 * jp],     a);
            pool[2 * jp + 1] = fmaxf(pool[2 * jp + 1], b);
            if (has1) {
                unpack2(accB[jp], a, b);
                pool[2 * jp]     = fmaxf(pool[2 * jp],     a);
                pool[2 * jp + 1] = fmaxf(pool[2 * jp + 1], b);
            }
        }
    }

#pragma unroll
    for (int j = 0; j < C1; j++) {
        int v = __float_as_int(pool[j]);           // pool >= 0 by construction
        v = __reduce_max_sync(0xffffffffu, v);
        if ((tx & 31) == 0) atomicMax(&spool[j], v);
    }
    __syncthreads();
    if (tx < C1) atomicMax(&d_poolmax[tx], spool[tx]);
}

// ---------------- branch 1 consumer-side: one warp per segment, no atomics ----------------
__global__ __launch_bounds__(256, 2)
void seg_kernel(const float* __restrict__ inp, int S)
{
    __shared__ ull sW1t[CIN * 32];   // transposed: [i][pair]  (conflict-free lane reads)
    __shared__ ull sb1s[32];

    const int tx = threadIdx.x;
    for (int i = tx; i < CIN * 32; i += 256) {
        int row = i >> 5, p = i & 31;
        sW1t[i] = ((const ull*)d_W1p)[p * CIN + row];
    }
    if (tx < 32) sb1s[tx] = ((const ull*)d_b1p)[tx];
    __syncthreads();

    const int gw = (blockIdx.x * 256 + tx) >> 5;   // segment id
    const int lane = tx & 31;                      // channel pair
    if (gw >= S) return;

    ull w[CIN];
#pragma unroll
    for (int i = 0; i < CIN; i++) w[i] = sW1t[(i << 5) | lane];
    const ull bias = sb1s[lane];

    const int s0 = d_start[gw], s1 = d_start[gw + 1];
    ull   sum2 = 0ull;
    float mx0 = 0.0f, mx1 = 0.0f;

    if (s0 < s1) {
        // 2-stage software pipeline: row index two ahead, row data one ahead
        int r  = d_order[s0];
        int rn = (s0 + 1 < s1) ? d_order[s0 + 1] : 0;
        const float4* ip = (const float4*)(inp + (size_t)r * CIN);
        float4 Va = ip[0], Vb = ip[1], Vc = ip[2], Vd = ip[3];

        for (int idx = s0; idx < s1; idx++) {
            int rn2 = (idx + 2 < s1) ? d_order[idx + 2] : 0;
            float4 Pa, Pb, Pc, Pd;
            if (idx + 1 < s1) {
                const float4* ipn = (const float4*)(inp + (size_t)rn * CIN);
                Pa = ipn[0]; Pb = ipn[1]; Pc = ipn[2]; Pd = ipn[3];
            }

            float xs[CIN] = {Va.x, Va.y, Va.z, Va.w, Vb.x, Vb.y, Vb.z, Vb.w,
                             Vc.x, Vc.y, Vc.z, Vc.w, Vd.x, Vd.y, Vd.z, Vd.w};
            ull a0 = bias, a1 = 0ull;
#pragma unroll
            for (int i = 0; i < CIN / 2; i++) {
                a0 = ffma2(pack2(xs[2 * i],     xs[2 * i]),     w[2 * i],     a0);
                a1 = ffma2(pack2(xs[2 * i + 1], xs[2 * i + 1]), w[2 * i + 1], a1);
            }
            a0 = fadd2(a0, a1);
            float x0, x1;
            unpack2(a0, x0, x1);
            x0 = fmaxf(x0, 0.0f);
            x1 = fmaxf(x1, 0.0f);
            sum2 = fadd2(sum2, pack2(x0, x1));
            mx0 = fmaxf(mx0, x0);
            mx1 = fmaxf(mx1, x1);

            r = rn; rn = rn2;
            Va = Pa; Vb = Pb; Vc = Pc; Vd = Pd;
        }
    }

    float sA, sB;
    unpack2(sum2, sA, sB);
    d_segsum[gw * C1 + 2 * lane]      = sA;
    d_segsum[gw * C1 + 2 * lane + 1]  = sB;
    d_segmaxf[gw * C1 + 2 * lane]     = mx0;   // >=0, empty segment -> 0 (matches clamp)
    d_segmaxf[gw * C1 + 2 * lane + 1] = mx1;
}

// ---------------- finalize: channel shuffle into output ----------------
__global__ void finalize_kernel(float* __restrict__ out, int S)
{
    int i = blockIdx.x * blockDim.x + threadIdx.x;
    if (i >= S * C1) return;
    int s = i / C1, c = i % C1;
    float sum = d_segsum[i];
    float mx  = d_segmaxf[i];
    float pl  = __int_as_float(d_poolmax[c]);
    float* o = out + (size_t)s * (3 * C1) + 3 * c;
    o[0] = sum;   // group_sum
    o[1] = mx;    // x_max
    o[2] = pl;    // max_pool broadcast
}

// ---------------- launch ----------------
extern "C" void kernel_launch(void* const* d_in, const int* in_sizes, int n_in,
                              void* d_out, int out_size)
{
    const float* inp = (const float*)d_in[0];
    const int*   seg = (const int*)d_in[1];
    const float* W1  = (const float*)d_in[3];
    const float* g1  = (const float*)d_in[4];
    const float* b1  = (const float*)d_in[5];
    const float* m1  = (const float*)d_in[6];
    const float* v1  = (const float*)d_in[7];
    const float* W2a = (const float*)d_in[8];
    const float* g2a = (const float*)d_in[9];
    const float* b2a = (const float*)d_in[10];
    const float* m2a = (const float*)d_in[11];
    const float* v2a = (const float*)d_in[12];
    const float* W2b = (const float*)d_in[13];
    const float* g2b = (const float*)d_in[14];
    const float* b2b = (const float*)d_in[15];
    const float* m2b = (const float*)d_in[16];
    const float* v2b = (const float*)d_in[17];

    int N = in_sizes[0] / CIN;
    if (N > MAXN) N = MAXN;
    int S = out_size / (3 * C1);
    if (S > MAXS) S = MAXS;

    fold_kernel<<<16, 256>>>(W1, g1, b1, m1, v1,
                             W2a, g2a, b2a, m2a, v2a,
                             W2b, g2b, b2b, m2b, v2b);

    hist_kernel<<<(N + 255) / 256, 256>>>(seg, N);
    scan_kernel<<<1, 1024>>>(S, N);
    scatter_kernel<<<(N + 255) / 256, 256>>>(seg, N);

    branch2_kernel<<<1184, 128>>>(inp, N);

    seg_kernel<<<(S * 32 + 255) / 256, 256>>>(inp, S);

    int ne = S * C1;
    finalize_kernel<<<(ne + 255) / 256, 256>>>((float*)d_out, S);
}